// round 8
// baseline (speedup 1.0000x reference)
#include <cuda_runtime.h>

// out[b,u] = prod_f(in[b,f]*w[f,u]) + bias[u] = P[b]*W[u] + bias[u]
// B=32768, F=32, U=256.
static constexpr int Bn = 32768;
static constexpr int Fn = 32;
static constexpr int Un = 256;

// Scratch for the 256 column products (no cudaMalloc allowed).
__device__ float g_W[Un];

// Kernel 1: W[u] = prod_f w[f,u]. One block of 256 threads; trivial cost.
__global__ void colprod_kernel(const float* __restrict__ w) {
    int u = threadIdx.x;
    float p = 1.0f;
#pragma unroll
    for (int f = 0; f < Fn; ++f) {
        p *= w[f * Un + u];   // coalesced across threads for each f
    }
    g_W[u] = p;
}

// Kernel 2: warp-autonomous rank-1 outer product. No smem, no barriers.
// Each warp handles 4 rows:
//   - 1 coalesced float4 input load (lane l -> row l>>3, 8 lanes/row)
//   - 3 shfl_xor -> per-row product in all 8 lanes of each group
//   - W/bias held in registers (lane l owns float4 columns l and l+32),
//     loaded independently of the input -> all 5 LDGs in flight at once
//   - per row: 1 shfl broadcast + 2 coalesced STG.128
// Warps retire as soon as their own stores drain; nothing cross-warp.
__global__ __launch_bounds__(256)
void outer_kernel(const float* __restrict__ in,
                  const float* __restrict__ bias,
                  float* __restrict__ out) {
    const int t    = threadIdx.x;
    const int lane = t & 31;
    // global warp id -> 4-row group
    const int gw   = (blockIdx.x << 3) + (t >> 5);
    const long long row0 = (long long)gw * 4;

    // Independent loads: input float4 + 2x W + 2x bias (5 LDGs, MLP=5).
    const float4* in4 = reinterpret_cast<const float4*>(in + row0 * Fn);
    const float4* W4  = reinterpret_cast<const float4*>(g_W);
    const float4* B4  = reinterpret_cast<const float4*>(bias);
    const float4 v   = in4[lane];          // 4 rows * 32 f = 32 float4
    const float4 wv0 = W4[lane];
    const float4 wv1 = W4[lane + 32];
    const float4 bv0 = B4[lane];
    const float4 bv1 = B4[lane + 32];

    float p = v.x * v.y * v.z * v.w;
    p *= __shfl_xor_sync(0xffffffffu, p, 1);
    p *= __shfl_xor_sync(0xffffffffu, p, 2);
    p *= __shfl_xor_sync(0xffffffffu, p, 4);
    // Now lanes 8r..8r+7 all hold the product of row (row0 + r).

    float4* out4 = reinterpret_cast<float4*>(out + row0 * Un);

#pragma unroll
    for (int r = 0; r < 4; ++r) {
        const float pr = __shfl_sync(0xffffffffu, p, r * 8);
        float4 o0, o1;
        o0.x = fmaf(pr, wv0.x, bv0.x);
        o0.y = fmaf(pr, wv0.y, bv0.y);
        o0.z = fmaf(pr, wv0.z, bv0.z);
        o0.w = fmaf(pr, wv0.w, bv0.w);
        o1.x = fmaf(pr, wv1.x, bv1.x);
        o1.y = fmaf(pr, wv1.y, bv1.y);
        o1.z = fmaf(pr, wv1.z, bv1.z);
        o1.w = fmaf(pr, wv1.w, bv1.w);
        // Row r occupies 64 float4; lane writes c4 = lane and lane+32.
        out4[(long long)r * 64 + lane]      = o0;
        out4[(long long)r * 64 + lane + 32] = o1;
    }
}

extern "C" void kernel_launch(void* const* d_in, const int* in_sizes, int n_in,
                              void* d_out, int out_size) {
    // metadata order: inputs [B,F], weight [F,U], weight_selector [F,U] (dead), bias [U]
    const float* in   = (const float*)d_in[0];
    const float* w    = (const float*)d_in[1];
    const float* bias = (const float*)d_in[3];
    float* out        = (float*)d_out;

    colprod_kernel<<<1, Un>>>(w);
    // 32768 rows / 4 rows-per-warp / 8 warps-per-block = 1024 blocks
    outer_kernel<<<Bn / 32, 256>>>(in, bias, out);
}

// round 10
// speedup vs baseline: 1.1603x; 1.1603x over previous
#include <cuda_runtime.h>

// out[b,u] = prod_f(in[b,f]*w[f,u]) + bias[u] = P[b]*W[u] + bias[u]
// B=32768, F=32, U=256.
static constexpr int Bn = 32768;
static constexpr int Fn = 32;
static constexpr int Un = 256;

// Single fused kernel. Block = 256 threads = 8 warps, 32 rows/block, grid 1024.
// Per block:
//   1. issue the per-warp input float4 load FIRST (DRAM latency overlaps phase 2)
//   2. all 256 threads compute W[u]=prod_f w[f,u] into smem
//      (32 coalesced loads/thread, 4 independent product chains for ILP;
//       redundant across blocks: 32MB of L2-hit traffic, rides free at L2=31%)
//   3. one __syncthreads
//   4. per-warp: shfl-reduce row products, read W from smem / bias from L2,
//      8 coalesced STG.128 per warp. No further cross-warp dependencies.
__global__ __launch_bounds__(256)
void fused_kernel(const float* __restrict__ in,
                  const float* __restrict__ w,
                  const float* __restrict__ bias,
                  float* __restrict__ out) {
    __shared__ float sW[Un];

    const int t    = threadIdx.x;
    const int lane = t & 31;
    const int gw   = (blockIdx.x << 3) + (t >> 5);   // global warp id
    const long long row0 = (long long)gw * 4;

    // (1) input load first: 4 rows * 32 f = 32 float4; lane l covers row l>>3
    const float4* in4 = reinterpret_cast<const float4*>(in + row0 * Fn);
    const float4 v = in4[lane];

    // (2) column products of w: thread t owns column t.
    // 4 independent chains -> 4-deep FMA-pipe ILP, 32 coalesced LDGs in flight.
    float p0 = 1.0f, p1 = 1.0f, p2 = 1.0f, p3 = 1.0f;
#pragma unroll
    for (int f = 0; f < Fn; f += 4) {
        p0 *= w[(f + 0) * Un + t];
        p1 *= w[(f + 1) * Un + t];
        p2 *= w[(f + 2) * Un + t];
        p3 *= w[(f + 3) * Un + t];
    }
    sW[t] = (p0 * p1) * (p2 * p3);

    // bias load: independent, overlaps everything above (L2-hit after wave 1)
    const float4* B4  = reinterpret_cast<const float4*>(bias);
    const float4 bv0 = B4[lane];
    const float4 bv1 = B4[lane + 32];

    __syncthreads();

    // (4) row products: reduce within 8-lane groups
    float p = v.x * v.y * v.z * v.w;
    p *= __shfl_xor_sync(0xffffffffu, p, 1);
    p *= __shfl_xor_sync(0xffffffffu, p, 2);
    p *= __shfl_xor_sync(0xffffffffu, p, 4);
    // lanes 8r..8r+7 now hold the product of row (row0 + r)

    // W from smem: float4 per lane, 512B/warp -> 4 conflict-free phases
    const float4* sW4 = reinterpret_cast<const float4*>(sW);
    const float4 wv0 = sW4[lane];
    const float4 wv1 = sW4[lane + 32];

    float4* out4 = reinterpret_cast<float4*>(out + row0 * Un);

#pragma unroll
    for (int r = 0; r < 4; ++r) {
        const float pr = __shfl_sync(0xffffffffu, p, r * 8);
        float4 o0, o1;
        o0.x = fmaf(pr, wv0.x, bv0.x);
        o0.y = fmaf(pr, wv0.y, bv0.y);
        o0.z = fmaf(pr, wv0.z, bv0.z);
        o0.w = fmaf(pr, wv0.w, bv0.w);
        o1.x = fmaf(pr, wv1.x, bv1.x);
        o1.y = fmaf(pr, wv1.y, bv1.y);
        o1.z = fmaf(pr, wv1.z, bv1.z);
        o1.w = fmaf(pr, wv1.w, bv1.w);
        // Row r occupies 64 float4; lane writes c4 = lane and lane+32.
        out4[(long long)r * 64 + lane]      = o0;
        out4[(long long)r * 64 + lane + 32] = o1;
    }
}

extern "C" void kernel_launch(void* const* d_in, const int* in_sizes, int n_in,
                              void* d_out, int out_size) {
    // metadata order: inputs [B,F], weight [F,U], weight_selector [F,U] (dead), bias [U]
    const float* in   = (const float*)d_in[0];
    const float* w    = (const float*)d_in[1];
    const float* bias = (const float*)d_in[3];
    float* out        = (float*)d_out;

    // 32768 rows / 4 rows-per-warp / 8 warps-per-block = 1024 blocks, ONE launch
    fused_kernel<<<Bn / 32, 256>>>(in, w, bias, out);
}